// round 10
// baseline (speedup 1.0000x reference)
#include <cuda_runtime.h>
#include <cstdint>
#include <math.h>

// Problem shape (fixed): B=4, H=8, S=1024, D=64
#define SLEN 1024
#define HD   64
#define NBH  32
#define NROWS (NBH * SLEN)           // 32768
#define NTOT  ((size_t)NROWS * SLEN) // 33554432 = 2^25
#define NBINS 4096                   // bits >> 18 : 8 exp + 5 mantissa bits

typedef unsigned long long ull;

// ---------------- scratch ---------------------------------------------------
__device__ float g_score[NROWS * SLEN];          // 128 MiB raw scores
__device__ unsigned int g_hist[NBINS];           // 16 KiB counts
__device__ float2 g_ttab2[NBINS];                // (t0, t1-t0) per bin
__device__ float g_invq[NROWS];
__device__ float g_invk[NROWS];

// ---------------- f32x2 helpers (sm_103a) -----------------------------------
__device__ __forceinline__ ull pack2(float a, float b) {
    ull r; asm("mov.b64 %0, {%1,%2};" : "=l"(r) : "f"(a), "f"(b)); return r;
}
__device__ __forceinline__ ull fma2(ull a, ull b, ull c) {
    ull d; asm("fma.rn.f32x2 %0, %1, %2, %3;" : "=l"(d) : "l"(a), "l"(b), "l"(c));
    return d;
}
__device__ __forceinline__ float2 unpack2(ull v) {
    float2 f; asm("mov.b64 {%0,%1}, %2;" : "=f"(f.x), "=f"(f.y) : "l"(v));
    return f;
}
__device__ __forceinline__ unsigned sw(unsigned a) {      // 128B-line swizzle
    return a ^ ((a >> 3) & 0x70u);
}

// ---------------- kernel 1: inverse row norms (+ hist zeroing) --------------
__global__ __launch_bounds__(256) void norms_kernel(const float* __restrict__ Q,
                                                    const float* __restrict__ K) {
    if (blockIdx.x < 16) g_hist[blockIdx.x * 256 + threadIdx.x] = 0u;
    int w = (blockIdx.x * 256 + threadIdx.x) >> 5;
    int lane = threadIdx.x & 31;
    const float* src; float* dst; int row;
    if (w < NROWS) { src = Q; dst = g_invq; row = w; }
    else           { src = K; dst = g_invk; row = w - NROWS; }
    const float* p = src + (size_t)row * HD;
    float a = p[lane], b = p[lane + 32];
    float s = a * a + b * b;
    #pragma unroll
    for (int o = 16; o; o >>= 1) s += __shfl_xor_sync(0xffffffffu, s, o);
    if (lane == 0) dst[row] = 1.0f / (sqrtf(s) + 1e-5f);
}

// ---------------- kernel 2: score GEMM + smem-private histogram -------------
// A staged k-major so the mainloop pulls a-values via LDS.128 (1 phase).
__global__ __launch_bounds__(256, 2) void score_kernel(const float* __restrict__ Q,
                                                       const float* __restrict__ K) {
    __shared__ __align__(16) float Qsk[32 * 132];  // [k][row], 16.9 KB (hist0 alias)
    __shared__ __align__(16) float Ks[32 * 128];   // k-major SW128 (hist1 alias)
    int bh = blockIdx.z;
    int i0 = blockIdx.y * 128, j0 = blockIdx.x * 128;
    const float* Qb = Q + (size_t)bh * SLEN * HD;
    const float* Kb = K + (size_t)bh * SLEN * HD;
    int tid = threadIdx.x;
    int tx = tid & 15, ty = tid >> 4;

    ull acc[8][4];
    #pragma unroll
    for (int ii = 0; ii < 8; ii++)
        #pragma unroll
        for (int p = 0; p < 4; p++) acc[ii][p] = 0ull;

    #pragma unroll
    for (int c = 0; c < 2; c++) {          // k chunks of 32 (ascending order!)
        int k0 = c * 32;
        if (c) __syncthreads();
        #pragma unroll
        for (int pass = 0; pass < 4; pass++) {
            int row = (tid >> 3) + pass * 32;
            int kq = (tid & 7) * 4;
            float4 q4 = *(const float4*)&Qb[(i0 + row) * HD + k0 + kq];
            Qsk[(kq + 0) * 132 + row] = q4.x;
            Qsk[(kq + 1) * 132 + row] = q4.y;
            Qsk[(kq + 2) * 132 + row] = q4.z;
            Qsk[(kq + 3) * 132 + row] = q4.w;
            float4 k4 = *(const float4*)&Kb[(j0 + row) * HD + k0 + kq];
            #pragma unroll
            for (int e = 0; e < 4; e++) {
                unsigned a = (unsigned)(kq + e) * 512u + (unsigned)row * 4u;
                Ks[sw(a) >> 2] = (&k4.x)[e];
            }
        }
        __syncthreads();
        #pragma unroll
        for (int k = 0; k < 32; k++) {
            unsigned a0 = (unsigned)k * 512u + (unsigned)tx * 32u;
            float4 b0 = *(const float4*)&Ks[sw(a0) >> 2];
            float4 b1 = *(const float4*)&Ks[sw(a0 + 16u) >> 2];
            ull bv0 = pack2(b0.x, b0.y), bv1 = pack2(b0.z, b0.w);
            ull bv2 = pack2(b1.x, b1.y), bv3 = pack2(b1.z, b1.w);
            float4 av0 = *(const float4*)&Qsk[k * 132 + ty * 8];
            float4 av1 = *(const float4*)&Qsk[k * 132 + ty * 8 + 4];
            const float* avp0 = &av0.x;
            const float* avp1 = &av1.x;
            #pragma unroll
            for (int ii = 0; ii < 4; ii++) {
                ull a2 = pack2(avp0[ii], avp0[ii]);
                acc[ii][0] = fma2(a2, bv0, acc[ii][0]);
                acc[ii][1] = fma2(a2, bv1, acc[ii][1]);
                acc[ii][2] = fma2(a2, bv2, acc[ii][2]);
                acc[ii][3] = fma2(a2, bv3, acc[ii][3]);
            }
            #pragma unroll
            for (int ii = 0; ii < 4; ii++) {
                ull a2 = pack2(avp1[ii], avp1[ii]);
                acc[4 + ii][0] = fma2(a2, bv0, acc[4 + ii][0]);
                acc[4 + ii][1] = fma2(a2, bv1, acc[4 + ii][1]);
                acc[4 + ii][2] = fma2(a2, bv2, acc[4 + ii][2]);
                acc[4 + ii][3] = fma2(a2, bv3, acc[4 + ii][3]);
            }
        }
    }

    // ---- epilogue: tiles dead; alias as two u16-packed lane-parity subhists --
    unsigned* hist0 = (unsigned*)Qsk;     // 2048 u32 = 4096 u16 counters
    unsigned* hist1 = (unsigned*)Ks;      // 2048 u32
    __syncthreads();
    for (int i = tid; i < 2048; i += 256) { hist0[i] = 0u; hist1[i] = 0u; }
    __syncthreads();
    unsigned* hsel = (tid & 1) ? hist1 : hist0;

    int jb = j0 + tx * 8;
    float ikv[8];
    #pragma unroll
    for (int jj = 0; jj < 8; jj++) ikv[jj] = g_invk[bh * SLEN + jb + jj];
    #pragma unroll
    for (int ii = 0; ii < 8; ii++) {
        int row = bh * SLEN + i0 + ty * 8 + ii;
        float iq = g_invq[row];
        float2 c0 = unpack2(acc[ii][0]);
        float2 c1 = unpack2(acc[ii][1]);
        float2 c2 = unpack2(acc[ii][2]);
        float2 c3 = unpack2(acc[ii][3]);
        float v[8];
        v[0] = c0.x * iq * ikv[0]; v[1] = c0.y * iq * ikv[1];
        v[2] = c1.x * iq * ikv[2]; v[3] = c1.y * iq * ikv[3];
        v[4] = c2.x * iq * ikv[4]; v[5] = c2.y * iq * ikv[5];
        v[6] = c3.x * iq * ikv[6]; v[7] = c3.y * iq * ikv[7];
        size_t idx = (size_t)row * SLEN + jb;
        *(float4*)&g_score[idx]     = make_float4(v[0], v[1], v[2], v[3]);
        *(float4*)&g_score[idx + 4] = make_float4(v[4], v[5], v[6], v[7]);
        #pragma unroll
        for (int e = 0; e < 8; e++) {
            unsigned bin = __float_as_uint(fabsf(v[e])) >> 18;   // < 4096
            atomicAdd(&hsel[bin >> 1], 1u << ((bin & 1u) * 16u));
        }
    }

    __syncthreads();
    for (int i = tid; i < 2048; i += 256) {
        unsigned p0 = hist0[i], p1 = hist1[i];
        unsigned lo = (p0 & 0xFFFFu) + (p1 & 0xFFFFu);
        unsigned hi = (p0 >> 16) + (p1 >> 16);
        if (lo) atomicAdd(&g_hist[2 * i],     lo);
        if (hi) atomicAdd(&g_hist[2 * i + 1], hi);
    }
}

// ---------------- kernel 2.5: scan 4096 bins + (t0, dt) edge table ----------
__global__ __launch_bounds__(1024) void scan_ttab_kernel() {
    __shared__ unsigned ws[32];
    int tid = threadIdx.x;
    int lane = tid & 31, wid = tid >> 5;
    unsigned c0 = g_hist[tid * 4], c1 = g_hist[tid * 4 + 1];
    unsigned c2 = g_hist[tid * 4 + 2], c3 = g_hist[tid * 4 + 3];
    unsigned tsum = c0 + c1 + c2 + c3;
    unsigned incl = tsum;
    #pragma unroll
    for (int o = 1; o < 32; o <<= 1) {
        unsigned n = __shfl_up_sync(0xffffffffu, incl, o);
        if (lane >= o) incl += n;
    }
    if (lane == 31) ws[wid] = incl;
    __syncthreads();
    if (wid == 0) {
        unsigned v = ws[lane];
        #pragma unroll
        for (int o = 1; o < 32; o <<= 1) {
            unsigned n = __shfl_up_sync(0xffffffffu, v, o);
            if (lane >= o) v += n;
        }
        ws[lane] = v;
    }
    __syncthreads();
    unsigned excl = incl - tsum + (wid ? ws[wid - 1] : 0u);
    const float sA = 1.0f / 33554431.0f;   // 1/(n-1)
    const float sB = 1.0f / 33554432.0f;   // 1/n
    unsigned e[5];
    e[0] = excl; e[1] = e[0] + c0; e[2] = e[1] + c1; e[3] = e[2] + c2; e[4] = e[3] + c3;
    float t[5];
    #pragma unroll
    for (int j = 0; j < 5; j++) t[j] = -__logf(fmaf((float)e[j], sA, sB));
    #pragma unroll
    for (int j = 0; j < 4; j++)
        g_ttab2[tid * 4 + j] = make_float2(t[j], t[j + 1] - t[j]);
}

// ---------------- kernel 3: fused transform + rowsum + out GEMM --------------
// 256 blocks x 128 rows, 2/SM, single wave. Coalesced staging: warp w reads the
// 32-col chunk of rows {w, w+8, ..., w+120} (lane = col); per-lane partial row
// sums, shfl-reduced at the end. T staged k-major -> LDS.128 a-loads.
__global__ __launch_bounds__(256, 2) void out_kernel(const float* __restrict__ V,
                                                     float* __restrict__ O) {
    extern __shared__ __align__(16) char dsm[];
    float*  Ts      = (float*)dsm;              // [32][132] k-major, 16.9 KB
    float*  Vs      = Ts + 32 * 132;            // [32][64] SW128, 8 KB
    float2* ttab2_s = (float2*)(Vs + 32 * 64);  // 4096 float2, 32 KB
    float*  sinv    = (float*)(ttab2_s + NBINS);// 128 floats

    int blk = blockIdx.x;                // 0..255
    int bh = blk >> 3;
    int i0 = blk * 128;
    const float* Vb = V + (size_t)bh * SLEN * HD;
    int tid = threadIdx.x;
    int tx = tid & 7, ty = tid >> 3;
    int lane = tid & 31, wrp = tid >> 5;

    for (int i = tid; i < NBINS; i += 256) ttab2_s[i] = g_ttab2[i];
    __syncthreads();

    ull acc[4][4];
    #pragma unroll
    for (int ii = 0; ii < 4; ii++)
        #pragma unroll
        for (int p = 0; p < 4; p++) acc[ii][p] = 0ull;
    float srow16[16];
    #pragma unroll
    for (int r = 0; r < 16; r++) srow16[r] = 0.0f;

    for (int c = 0; c < 32; c++) {   // k chunks of 32
        if (c) __syncthreads();
        // stage V chunk (swizzled): 32 rows x 64 cols
        {
            int kv = tid >> 3;
            int d8 = (tid & 7) * 8;
            const float* vp = &Vb[(c * 32 + kv) * HD + d8];
            #pragma unroll
            for (int h = 0; h < 2; h++) {
                float4 v4 = *(const float4*)&vp[h * 4];
                unsigned a = (unsigned)kv * 256u + (unsigned)(d8 + h * 4) * 4u;
                *(float4*)&Vs[sw(a) >> 2] = v4;
            }
        }
        // stage + transform P (coalesced: lane = col, 16 rows per thread)
        {
            const float* pc = g_score + (size_t)i0 * SLEN + c * 32 + lane;
            #pragma unroll
            for (int r = 0; r < 16; r++) {
                int row = wrp + r * 8;
                float v = __ldg(pc + (size_t)row * SLEN);
                unsigned bits = __float_as_uint(fabsf(v));
                unsigned b = bits >> 18;
                float frac = (float)(bits & 0x3FFFFu) * (1.0f / 262144.0f);
                float2 tt = ttab2_s[b];
                float t = fmaf(frac, tt.y, tt.x);
                t = (v > 0.0f) ? t : ((v < 0.0f) ? -t : 0.0f);
                srow16[r] += fabsf(t);
                Ts[lane * 132 + row] = t;
            }
        }
        __syncthreads();
        #pragma unroll
        for (int k = 0; k < 32; k++) {
            unsigned a0 = (unsigned)k * 256u + (unsigned)tx * 32u;
            float4 b0 = *(const float4*)&Vs[sw(a0) >> 2];
            float4 b1 = *(const float4*)&Vs[sw(a0 + 16u) >> 2];
            ull bv0 = pack2(b0.x, b0.y), bv1 = pack2(b0.z, b0.w);
            ull bv2 = pack2(b1.x, b1.y), bv3 = pack2(b1.z, b1.w);
            float4 av = *(const float4*)&Ts[k * 132 + ty * 4];
            const float* avp = &av.x;
            #pragma unroll
            for (int ii = 0; ii < 4; ii++) {
                ull a2 = pack2(avp[ii], avp[ii]);
                acc[ii][0] = fma2(a2, bv0, acc[ii][0]);
                acc[ii][1] = fma2(a2, bv1, acc[ii][1]);
                acc[ii][2] = fma2(a2, bv2, acc[ii][2]);
                acc[ii][3] = fma2(a2, bv3, acc[ii][3]);
            }
        }
    }

    // row L1 sums: reduce per-lane partials (warp w owns rows w, w+8, ...)
    #pragma unroll
    for (int r = 0; r < 16; r++) {
        float s = srow16[r];
        #pragma unroll
        for (int o = 16; o; o >>= 1) s += __shfl_xor_sync(0xffffffffu, s, o);
        if (lane == 0) sinv[wrp + r * 8] = 1.0f / s;
    }
    __syncthreads();

    int d0 = tx * 8;
    #pragma unroll
    for (int ii = 0; ii < 4; ii++) {
        int lrow = ty * 4 + ii;
        float s = sinv[lrow];
        float2 c0 = unpack2(acc[ii][0]);
        float2 c1 = unpack2(acc[ii][1]);
        float2 c2 = unpack2(acc[ii][2]);
        float2 c3 = unpack2(acc[ii][3]);
        size_t oidx = (size_t)(i0 + lrow) * HD + d0;
        *(float4*)&O[oidx]     = make_float4(c0.x * s, c0.y * s, c1.x * s, c1.y * s);
        *(float4*)&O[oidx + 4] = make_float4(c2.x * s, c2.y * s, c3.x * s, c3.y * s);
    }
}

// ---------------- launcher ---------------------------------------------------
#define SMEM_OUT ((32 * 132 + 32 * 64 + 128) * 4 + NBINS * 8)

extern "C" void kernel_launch(void* const* d_in, const int* in_sizes, int n_in,
                              void* d_out, int out_size) {
    const float* Q = (const float*)d_in[0];
    const float* K = (const float*)d_in[1];
    const float* V = (const float*)d_in[2];
    float* O = (float*)d_out;

    static int attr_done = 0;
    if (!attr_done) {
        cudaFuncSetAttribute(out_kernel,
                             cudaFuncAttributeMaxDynamicSharedMemorySize, SMEM_OUT);
        attr_done = 1;
    }

    norms_kernel<<<8192, 256>>>(Q, K);
    score_kernel<<<dim3(8, 8, NBH), 256>>>(Q, K);
    scan_ttab_kernel<<<1, 1024>>>();
    out_kernel<<<256, 256, SMEM_OUT>>>(V, O);
}